// round 16
// baseline (speedup 1.0000x reference)
#include <cuda_runtime.h>
#include <math.h>
#include <stdint.h>

#define Bdim 4
#define Sdim 2048
#define Ddim 768
#define Edim 8
#define Hdim 3072
#define NTOK (Bdim * Sdim)        // 8192
#define NDISP (NTOK * 2)          // 16384
#define MAXTILES 144
#define KSPLIT 5                  // ffn2 K-split
#define K1SPLIT 2                 // ffn1 K-split (bufferless: disjoint outputs)

// ---------------- scratch ------------------------------------------------------
__device__ int   g_cnt[Edim];
__device__ int   g_off[Edim];
__device__ int   g_cur[Edim];
__device__ int   g_ntiles;
__device__ int   g_tile_e[MAXTILES];
__device__ int   g_tile_m[MAXTILES];
__device__ int   g_top_e[NDISP];
__device__ float g_top_g[NDISP];
__device__ int   g_tok[NDISP];
__device__ float g_gate[NDISP];
__device__ int   g_pos[NDISP];
__device__ float g_h [(size_t)NDISP * Hdim];  // raw partial sums, K[0:384)
__device__ float g_h2[(size_t)NDISP * Hdim];  // raw partial sums, K[384:768)
__device__ float g_yd[(size_t)NDISP * Ddim];  // atomic accumulation target

// ---------------- f32x2 helpers -------------------------------------------------
__device__ __forceinline__ unsigned long long pack2(float a) {
    unsigned long long r;
    asm("mov.b64 %0, {%1, %1};" : "=l"(r) : "r"(__float_as_uint(a)));
    return r;
}
__device__ __forceinline__ void fma2(unsigned long long& d, unsigned long long a,
                                     unsigned long long b) {
    asm("fma.rn.f32x2 %0, %1, %2, %0;" : "+l"(d) : "l"(a), "l"(b));
}
__device__ __forceinline__ float2 unpack2(unsigned long long v) {
    uint32_t lo, hi;
    asm("mov.b64 {%0, %1}, %2;" : "=r"(lo), "=r"(hi) : "l"(v));
    float2 f;
    f.x = __uint_as_float(lo);
    f.y = __uint_as_float(hi);
    return f;
}

// ---------------- kernel 0: zero counters ----------------------------------------
__global__ void zero_kernel() {
    int t = threadIdx.x;
    if (t < Edim) g_cnt[t] = 0;
}

// ---------------- kernel 0b: zero yd ----------------------------------------------
__global__ void yzero_kernel() {
    size_t idx = (size_t)blockIdx.x * blockDim.x + threadIdx.x;
    size_t total = (size_t)NDISP * Ddim / 4;
    if (idx >= total) return;
    *(float4*)(g_yd + idx * 4) = make_float4(0.f, 0.f, 0.f, 0.f);
}

// ---------------- kernel 1: router (1 warp per token) ---------------------------
__global__ void router_kernel(const float* __restrict__ x,
                              const float* __restrict__ noise,
                              const float* __restrict__ w_route,
                              const float* __restrict__ b_route,
                              const float* __restrict__ w_noise,
                              const float* __restrict__ b_noise) {
    int warp = (blockIdx.x * blockDim.x + threadIdx.x) >> 5;
    int lane = threadIdx.x & 31;
    if (warp >= NTOK) return;
    const float* xr = x + (size_t)warp * Ddim;
    float ar[Edim], an[Edim];
#pragma unroll
    for (int e = 0; e < Edim; e++) { ar[e] = 0.f; an[e] = 0.f; }
    for (int k = lane; k < Ddim; k += 32) {
        float xv = xr[k];
        const float* wr = w_route + (size_t)k * Edim;
        const float* wn = w_noise + (size_t)k * Edim;
#pragma unroll
        for (int e = 0; e < Edim; e++) { ar[e] += xv * wr[e]; an[e] += xv * wn[e]; }
    }
#pragma unroll
    for (int e = 0; e < Edim; e++) {
#pragma unroll
        for (int o = 16; o > 0; o >>= 1) {
            ar[e] += __shfl_down_sync(0xffffffffu, ar[e], o);
            an[e] += __shfl_down_sync(0xffffffffu, an[e], o);
        }
    }
    if (lane == 0) {
        float nv[Edim];
#pragma unroll
        for (int e = 0; e < Edim; e++) {
            float z = an[e] + b_noise[e];
            float sp = (z > 0.f) ? (z + log1pf(expf(-z))) : log1pf(expf(z));
            nv[e] = ar[e] + b_route[e] + noise[(size_t)warp * Edim + e] * sp;
        }
        int i1 = 0;
#pragma unroll
        for (int e = 1; e < Edim; e++) if (nv[e] > nv[i1]) i1 = e;
        int i2 = -1;
#pragma unroll
        for (int e = 0; e < Edim; e++) {
            if (e == i1) continue;
            if (i2 < 0 || nv[e] > nv[i2]) i2 = e;
        }
        float d = nv[i2] - nv[i1];
        float ex = expf(d);
        float g1 = 1.f / (1.f + ex);
        float g2 = ex / (1.f + ex);
        g_top_e[warp * 2 + 0] = i1;  g_top_g[warp * 2 + 0] = g1;
        g_top_e[warp * 2 + 1] = i2;  g_top_g[warp * 2 + 1] = g2;
        atomicAdd(&g_cnt[i1], 1);
        atomicAdd(&g_cnt[i2], 1);
    }
}

// ---------------- kernel 2: prefix scan + compact tile list ---------------------
__global__ void scan_kernel() {
    if (threadIdx.x == 0) {
        int acc = 0;
        for (int e = 0; e < Edim; e++) { g_off[e] = acc; g_cur[e] = acc; acc += g_cnt[e]; }
        int nt = 0;
        for (int e = 0; e < Edim; e++) {
            int tiles = (g_cnt[e] + 127) >> 7;
            for (int t = 0; t < tiles; t++) {
                g_tile_e[nt] = e;
                g_tile_m[nt] = t;
                nt++;
            }
        }
        g_ntiles = nt;
    }
}

// ---------------- kernel 3: fill dispatch lists ----------------------------------
__global__ void fill_kernel() {
    int idx = blockIdx.x * blockDim.x + threadIdx.x;
    if (idx >= NDISP) return;
    int t = idx >> 1;
    int e = g_top_e[idx];
    int pos = atomicAdd(&g_cur[e], 1);
    g_tok[pos] = t;
    g_gate[pos] = g_top_g[idx];
    g_pos[idx] = pos;
}

// ---------------- kernel 4: GEMM1 (K-split x2, raw sums, disjoint buffers) ------
__global__ void __launch_bounds__(256, 2)
ffn1_kernel(const float* __restrict__ x,
            const float* __restrict__ W1) {
    int ty = blockIdx.y;
    if (ty >= g_ntiles) return;
    int e = g_tile_e[ty];
    int cnt = g_cnt[e];
    int m0 = g_tile_m[ty] << 7;
    int base = g_off[e];
    int n0 = blockIdx.x * 128;
    int z = blockIdx.z;                      // K half
    int kbase = z * (Ddim / K1SPLIT);        // 0 or 384
    const float* Bp = W1 + (size_t)e * Ddim * Hdim;

    __shared__ float As[2][16][132];
    __shared__ float Bs[2][16][128];
    __shared__ int rows[128];

    int tid = threadIdx.x;
    if (tid < 128) {
        int r = m0 + tid;
        rows[tid] = (r < cnt) ? g_tok[base + r] : -1;
    }
    __syncthreads();

    int arow = tid >> 1, akc = (tid & 1) * 8;
    int bkr = tid >> 4, bnc = (tid & 15) * 8;
    int tm = (tid >> 4) * 8, tn = (tid & 15) * 8;

    unsigned long long acc[8][4];
#pragma unroll
    for (int i = 0; i < 8; i++)
#pragma unroll
        for (int j = 0; j < 4; j++) acc[i][j] = 0ull;

    int trow = rows[arow];
    const float* ap_base = (trow >= 0) ? (x + (size_t)trow * Ddim + kbase + akc) : nullptr;
    const float* bp_base = Bp + (size_t)(kbase + bkr) * Hdim + n0 + bnc;

    float4 av0 = make_float4(0.f, 0.f, 0.f, 0.f), av1 = av0;
    if (ap_base) {
        av0 = *(const float4*)(ap_base);
        av1 = *(const float4*)(ap_base + 4);
    }
    float4 bv0 = *(const float4*)(bp_base);
    float4 bv1 = *(const float4*)(bp_base + 4);

    As[0][akc + 0][arow] = av0.x;  As[0][akc + 1][arow] = av0.y;
    As[0][akc + 2][arow] = av0.z;  As[0][akc + 3][arow] = av0.w;
    As[0][akc + 4][arow] = av1.x;  As[0][akc + 5][arow] = av1.y;
    As[0][akc + 6][arow] = av1.z;  As[0][akc + 7][arow] = av1.w;
    *(float4*)&Bs[0][bkr][bnc]     = bv0;
    *(float4*)&Bs[0][bkr][bnc + 4] = bv1;
    __syncthreads();

    constexpr int NC = (Ddim / K1SPLIT) / 16;   // 24
    for (int c = 0; c < NC; c++) {
        int cur = c & 1, nxt = cur ^ 1;
        if (c + 1 < NC) {
            int k0 = (c + 1) * 16;
            if (ap_base) {
                av0 = *(const float4*)(ap_base + k0);
                av1 = *(const float4*)(ap_base + k0 + 4);
            }
            const float* bp = bp_base + (size_t)k0 * Hdim;
            bv0 = *(const float4*)(bp);
            bv1 = *(const float4*)(bp + 4);
        }
#pragma unroll
        for (int kk = 0; kk < 16; kk++) {
            float4 aA = *(const float4*)&As[cur][kk][tm];
            float4 aB = *(const float4*)&As[cur][kk][tm + 4];
            ulonglong2 bA = *(const ulonglong2*)&Bs[cur][kk][tn];
            ulonglong2 bB = *(const ulonglong2*)&Bs[cur][kk][tn + 4];
            unsigned long long b2[4] = {bA.x, bA.y, bB.x, bB.y};
            float a[8] = {aA.x, aA.y, aA.z, aA.w, aB.x, aB.y, aB.z, aB.w};
#pragma unroll
            for (int i = 0; i < 8; i++) {
                unsigned long long ai = pack2(a[i]);
#pragma unroll
                for (int j = 0; j < 4; j++) fma2(acc[i][j], ai, b2[j]);
            }
        }
        if (c + 1 < NC) {
            As[nxt][akc + 0][arow] = av0.x;  As[nxt][akc + 1][arow] = av0.y;
            As[nxt][akc + 2][arow] = av0.z;  As[nxt][akc + 3][arow] = av0.w;
            As[nxt][akc + 4][arow] = av1.x;  As[nxt][akc + 5][arow] = av1.y;
            As[nxt][akc + 6][arow] = av1.z;  As[nxt][akc + 7][arow] = av1.w;
            *(float4*)&Bs[nxt][bkr][bnc]     = bv0;
            *(float4*)&Bs[nxt][bkr][bnc + 4] = bv1;
        }
        __syncthreads();
    }

    // raw partial sums (no bias, no relu) into z's private buffer
    float* outh = z ? g_h2 : g_h;
#pragma unroll
    for (int i = 0; i < 8; i++) {
        int r = m0 + tm + i;
        if (r < cnt) {
            float* hp = outh + (size_t)(base + r) * Hdim + n0 + tn;
#pragma unroll
            for (int j = 0; j < 4; j++) {
                float2 v = unpack2(acc[i][j]);
                *(float2*)(hp + j * 2) = v;
            }
        }
    }
}

// ---------------- kernel 5: GEMM2 (K-split x5, fused relu(h0+h1+b1) load) -------
__global__ void __launch_bounds__(256, 2)
ffn2_kernel(const float* __restrict__ W2,
            const float* __restrict__ b1,
            const float* __restrict__ b2) {
    int ty = blockIdx.y;
    if (ty >= g_ntiles) return;
    int e = g_tile_e[ty];
    int cnt = g_cnt[e];
    int m0 = g_tile_m[ty] << 7;
    int base = g_off[e];
    int n0 = blockIdx.x * 128;
    int z = blockIdx.z;
    int cstart = (z < 2) ? z * 39 : 78 + (z - 2) * 38;
    int NC = (z < 2) ? 39 : 38;
    int kbase = cstart * 16;

    const float* Bp = W2 + (size_t)e * Hdim * Ddim;

    __shared__ float As[2][16][132];
    __shared__ float Bs[2][16][128];

    int tid = threadIdx.x;
    int arow = tid >> 1, akc = (tid & 1) * 8;
    int bkr = tid >> 4, bnc = (tid & 15) * 8;
    int tm = (tid >> 4) * 8, tn = (tid & 15) * 8;

    int r_a = m0 + arow;
    if (r_a >= cnt) r_a = cnt - 1;
    size_t aoff = (size_t)(base + r_a) * Hdim + kbase + akc;
    const float* ah_base = g_h + aoff;
    const float* aw_base = g_h2 + aoff;
    const float* b1_base = b1 + (size_t)e * Hdim + kbase + akc;
    const float* bp_base = Bp + (size_t)(kbase + bkr) * Ddim + n0 + bnc;

    unsigned long long acc[8][4];
#pragma unroll
    for (int i = 0; i < 8; i++)
#pragma unroll
        for (int j = 0; j < 4; j++) acc[i][j] = 0ull;

    // fused A load: relu(h0 + h1 + b1)
    auto load_a = [&](int k0, float4& o0, float4& o1) {
        float4 h0a = *(const float4*)(ah_base + k0);
        float4 h0b = *(const float4*)(ah_base + k0 + 4);
        float4 h1a = *(const float4*)(aw_base + k0);
        float4 h1b = *(const float4*)(aw_base + k0 + 4);
        float4 bba = *(const float4*)(b1_base + k0);
        float4 bbb = *(const float4*)(b1_base + k0 + 4);
        o0.x = fmaxf(h0a.x + h1a.x + bba.x, 0.f);
        o0.y = fmaxf(h0a.y + h1a.y + bba.y, 0.f);
        o0.z = fmaxf(h0a.z + h1a.z + bba.z, 0.f);
        o0.w = fmaxf(h0a.w + h1a.w + bba.w, 0.f);
        o1.x = fmaxf(h0b.x + h1b.x + bbb.x, 0.f);
        o1.y = fmaxf(h0b.y + h1b.y + bbb.y, 0.f);
        o1.z = fmaxf(h0b.z + h1b.z + bbb.z, 0.f);
        o1.w = fmaxf(h0b.w + h1b.w + bbb.w, 0.f);
    };

    float4 av0, av1;
    load_a(0, av0, av1);
    float4 bv0 = *(const float4*)(bp_base);
    float4 bv1 = *(const float4*)(bp_base + 4);

    As[0][akc + 0][arow] = av0.x;  As[0][akc + 1][arow] = av0.y;
    As[0][akc + 2][arow] = av0.z;  As[0][akc + 3][arow] = av0.w;
    As[0][akc + 4][arow] = av1.x;  As[0][akc + 5][arow] = av1.y;
    As[0][akc + 6][arow] = av1.z;  As[0][akc + 7][arow] = av1.w;
    *(float4*)&Bs[0][bkr][bnc]     = bv0;
    *(float4*)&Bs[0][bkr][bnc + 4] = bv1;
    __syncthreads();

    for (int c = 0; c < NC; c++) {
        int cur = c & 1, nxt = cur ^ 1;
        if (c + 1 < NC) {
            int k0 = (c + 1) * 16;
            load_a(k0, av0, av1);
            const float* bp = bp_base + (size_t)k0 * Ddim;
            bv0 = *(const float4*)(bp);
            bv1 = *(const float4*)(bp + 4);
        }
#pragma unroll
        for (int kk = 0; kk < 16; kk++) {
            float4 aA = *(const float4*)&As[cur][kk][tm];
            float4 aB = *(const float4*)&As[cur][kk][tm + 4];
            ulonglong2 bA = *(const ulonglong2*)&Bs[cur][kk][tn];
            ulonglong2 bB = *(const ulonglong2*)&Bs[cur][kk][tn + 4];
            unsigned long long b2v[4] = {bA.x, bA.y, bB.x, bB.y};
            float a[8] = {aA.x, aA.y, aA.z, aA.w, aB.x, aB.y, aB.z, aB.w};
#pragma unroll
            for (int i = 0; i < 8; i++) {
                unsigned long long ai = pack2(a[i]);
#pragma unroll
                for (int j = 0; j < 4; j++) fma2(acc[i][j], ai, b2v[j]);
            }
        }
        if (c + 1 < NC) {
            As[nxt][akc + 0][arow] = av0.x;  As[nxt][akc + 1][arow] = av0.y;
            As[nxt][akc + 2][arow] = av0.z;  As[nxt][akc + 3][arow] = av0.w;
            As[nxt][akc + 4][arow] = av1.x;  As[nxt][akc + 5][arow] = av1.y;
            As[nxt][akc + 6][arow] = av1.z;  As[nxt][akc + 7][arow] = av1.w;
            *(float4*)&Bs[nxt][bkr][bnc]     = bv0;
            *(float4*)&Bs[nxt][bkr][bnc + 4] = bv1;
        }
        __syncthreads();
    }

    const float* b2p = b2 + (size_t)e * Ddim + n0 + tn;
#pragma unroll
    for (int i = 0; i < 8; i++) {
        int r = m0 + tm + i;
        if (r < cnt) {
            float g = g_gate[base + r];
            float* yp = g_yd + (size_t)(base + r) * Ddim + n0 + tn;
#pragma unroll
            for (int j = 0; j < 4; j++) {
                float2 v = unpack2(acc[i][j]);
                float p0 = g * v.x;
                float p1 = g * v.y;
                if (z == 0) {
                    p0 += g * b2p[j * 2 + 0];
                    p1 += g * b2p[j * 2 + 1];
                }
                atomicAdd(yp + j * 2 + 0, p0);
                atomicAdd(yp + j * 2 + 1, p1);
            }
        }
    }
}

// ---------------- kernel 6: combine ---------------------------------------------
__global__ void combine_kernel(float* __restrict__ out) {
    int idx = blockIdx.x * blockDim.x + threadIdx.x;
    int total = NTOK * Ddim / 4;
    if (idx >= total) return;
    int t = idx / (Ddim / 4);
    int d4 = idx % (Ddim / 4);
    int p0 = g_pos[t * 2 + 0];
    int p1 = g_pos[t * 2 + 1];
    float4 a = *(const float4*)(g_yd + (size_t)p0 * Ddim + d4 * 4);
    float4 b = *(const float4*)(g_yd + (size_t)p1 * Ddim + d4 * 4);
    float4 o;
    o.x = a.x + b.x; o.y = a.y + b.y; o.z = a.z + b.z; o.w = a.w + b.w;
    *(float4*)(out + (size_t)t * Ddim + d4 * 4) = o;
}

// ---------------- launch ---------------------------------------------------------
extern "C" void kernel_launch(void* const* d_in, const int* in_sizes, int n_in,
                              void* d_out, int out_size) {
    const float* x       = (const float*)d_in[0];
    const float* noise   = (const float*)d_in[1];
    const float* w_route = (const float*)d_in[2];
    const float* b_route = (const float*)d_in[3];
    const float* w_noise = (const float*)d_in[4];
    const float* b_noise = (const float*)d_in[5];
    const float* W1      = (const float*)d_in[6];
    const float* b1      = (const float*)d_in[7];
    const float* W2      = (const float*)d_in[8];
    const float* b2      = (const float*)d_in[9];
    float* out = (float*)d_out;

    zero_kernel<<<1, 32>>>();
    router_kernel<<<NTOK / 8, 256>>>(x, noise, w_route, b_route, w_noise, b_noise);
    scan_kernel<<<1, 1>>>();
    fill_kernel<<<(NDISP + 255) / 256, 256>>>();
    yzero_kernel<<<(NDISP * (Ddim / 4) + 255) / 256, 256>>>();
    ffn1_kernel<<<dim3(Hdim / 128, MAXTILES, K1SPLIT), 256>>>(x, W1);
    ffn2_kernel<<<dim3(Ddim / 128, MAXTILES, KSPLIT), 256>>>(W2, b1, b2);
    combine_kernel<<<(NTOK * Ddim / 4 + 255) / 256, 256>>>(out);
}

// round 17
// speedup vs baseline: 1.0849x; 1.0849x over previous
#include <cuda_runtime.h>
#include <math.h>
#include <stdint.h>

#define Bdim 4
#define Sdim 2048
#define Ddim 768
#define Edim 8
#define Hdim 3072
#define NTOK (Bdim * Sdim)        // 8192
#define NDISP (NTOK * 2)          // 16384
#define MAXTILES 144
#define KSPLIT 5

// ---------------- scratch ------------------------------------------------------
__device__ int   g_cnt[Edim];
__device__ int   g_off[Edim];
__device__ int   g_cur[Edim];
__device__ int   g_ntiles;
__device__ int   g_tile_e[MAXTILES];
__device__ int   g_tile_m[MAXTILES];
__device__ int   g_top_e[NDISP];
__device__ float g_top_g[NDISP];
__device__ int   g_tok[NDISP];
__device__ float g_gate[NDISP];
__device__ int   g_pos[NDISP];
__device__ float g_h[(size_t)NDISP * Hdim];   // 201 MB intermediate activations
__device__ float g_yd[(size_t)NDISP * Ddim];  // 50 MB (atomic accumulation target)

// ---------------- f32x2 helpers -------------------------------------------------
__device__ __forceinline__ unsigned long long pack2(float a) {
    unsigned long long r;
    asm("mov.b64 %0, {%1, %1};" : "=l"(r) : "r"(__float_as_uint(a)));
    return r;
}
__device__ __forceinline__ void fma2(unsigned long long& d, unsigned long long a,
                                     unsigned long long b) {
    asm("fma.rn.f32x2 %0, %1, %2, %0;" : "+l"(d) : "l"(a), "l"(b));
}
__device__ __forceinline__ float2 unpack2(unsigned long long v) {
    uint32_t lo, hi;
    asm("mov.b64 {%0, %1}, %2;" : "=r"(lo), "=r"(hi) : "l"(v));
    float2 f;
    f.x = __uint_as_float(lo);
    f.y = __uint_as_float(hi);
    return f;
}

// ---------------- kernel 0: zero counters ----------------------------------------
__global__ void zero_kernel() {
    int t = threadIdx.x;
    if (t < Edim) g_cnt[t] = 0;
}

// ---------------- kernel 0b: zero yd ----------------------------------------------
__global__ void yzero_kernel() {
    size_t idx = (size_t)blockIdx.x * blockDim.x + threadIdx.x;
    size_t total = (size_t)NDISP * Ddim / 4;
    if (idx >= total) return;
    *(float4*)(g_yd + idx * 4) = make_float4(0.f, 0.f, 0.f, 0.f);
}

// ---------------- kernel 1: router (1 warp per token) ---------------------------
__global__ void router_kernel(const float* __restrict__ x,
                              const float* __restrict__ noise,
                              const float* __restrict__ w_route,
                              const float* __restrict__ b_route,
                              const float* __restrict__ w_noise,
                              const float* __restrict__ b_noise) {
    int warp = (blockIdx.x * blockDim.x + threadIdx.x) >> 5;
    int lane = threadIdx.x & 31;
    if (warp >= NTOK) return;
    const float* xr = x + (size_t)warp * Ddim;
    float ar[Edim], an[Edim];
#pragma unroll
    for (int e = 0; e < Edim; e++) { ar[e] = 0.f; an[e] = 0.f; }
    for (int k = lane; k < Ddim; k += 32) {
        float xv = xr[k];
        const float* wr = w_route + (size_t)k * Edim;
        const float* wn = w_noise + (size_t)k * Edim;
#pragma unroll
        for (int e = 0; e < Edim; e++) { ar[e] += xv * wr[e]; an[e] += xv * wn[e]; }
    }
#pragma unroll
    for (int e = 0; e < Edim; e++) {
#pragma unroll
        for (int o = 16; o > 0; o >>= 1) {
            ar[e] += __shfl_down_sync(0xffffffffu, ar[e], o);
            an[e] += __shfl_down_sync(0xffffffffu, an[e], o);
        }
    }
    if (lane == 0) {
        float nv[Edim];
#pragma unroll
        for (int e = 0; e < Edim; e++) {
            float z = an[e] + b_noise[e];
            float sp = (z > 0.f) ? (z + log1pf(expf(-z))) : log1pf(expf(z));
            nv[e] = ar[e] + b_route[e] + noise[(size_t)warp * Edim + e] * sp;
        }
        int i1 = 0;
#pragma unroll
        for (int e = 1; e < Edim; e++) if (nv[e] > nv[i1]) i1 = e;
        int i2 = -1;
#pragma unroll
        for (int e = 0; e < Edim; e++) {
            if (e == i1) continue;
            if (i2 < 0 || nv[e] > nv[i2]) i2 = e;
        }
        float d = nv[i2] - nv[i1];
        float ex = expf(d);
        float g1 = 1.f / (1.f + ex);
        float g2 = ex / (1.f + ex);
        g_top_e[warp * 2 + 0] = i1;  g_top_g[warp * 2 + 0] = g1;
        g_top_e[warp * 2 + 1] = i2;  g_top_g[warp * 2 + 1] = g2;
        atomicAdd(&g_cnt[i1], 1);
        atomicAdd(&g_cnt[i2], 1);
    }
}

// ---------------- kernel 2: prefix scan + compact tile list ---------------------
__global__ void scan_kernel() {
    if (threadIdx.x == 0) {
        int acc = 0;
        for (int e = 0; e < Edim; e++) { g_off[e] = acc; g_cur[e] = acc; acc += g_cnt[e]; }
        int nt = 0;
        for (int e = 0; e < Edim; e++) {
            int tiles = (g_cnt[e] + 127) >> 7;
            for (int t = 0; t < tiles; t++) {
                g_tile_e[nt] = e;
                g_tile_m[nt] = t;
                nt++;
            }
        }
        g_ntiles = nt;
    }
}

// ---------------- kernel 3: fill dispatch lists ----------------------------------
__global__ void fill_kernel() {
    int idx = blockIdx.x * blockDim.x + threadIdx.x;
    if (idx >= NDISP) return;
    int t = idx >> 1;
    int e = g_top_e[idx];
    int pos = atomicAdd(&g_cur[e], 1);
    g_tok[pos] = t;
    g_gate[pos] = g_top_g[idx];
    g_pos[idx] = pos;
}

// ---------------- kernel 4: GEMM1 (128x128, double-buffered, compact grid) ------
__global__ void __launch_bounds__(256, 2)
ffn1_kernel(const float* __restrict__ x,
            const float* __restrict__ W1,
            const float* __restrict__ b1) {
    int ty = blockIdx.y;
    if (ty >= g_ntiles) return;
    int e = g_tile_e[ty];
    int cnt = g_cnt[e];
    int m0 = g_tile_m[ty] << 7;
    int base = g_off[e];
    int n0 = blockIdx.x * 128;
    const float* Bp = W1 + (size_t)e * Ddim * Hdim;

    __shared__ float As[2][16][132];
    __shared__ float Bs[2][16][128];
    __shared__ int rows[128];

    int tid = threadIdx.x;
    if (tid < 128) {
        int r = m0 + tid;
        rows[tid] = (r < cnt) ? g_tok[base + r] : -1;
    }
    __syncthreads();

    int arow = tid >> 1, akc = (tid & 1) * 8;
    int bkr = tid >> 4, bnc = (tid & 15) * 8;
    int tm = (tid >> 4) * 8, tn = (tid & 15) * 8;

    unsigned long long acc[8][4];
#pragma unroll
    for (int i = 0; i < 8; i++)
#pragma unroll
        for (int j = 0; j < 4; j++) acc[i][j] = 0ull;

    int trow = rows[arow];
    const float* ap_base = (trow >= 0) ? (x + (size_t)trow * Ddim + akc) : nullptr;
    const float* bp_base = Bp + (size_t)bkr * Hdim + n0 + bnc;

    float4 av0 = make_float4(0.f, 0.f, 0.f, 0.f), av1 = av0;
    if (ap_base) {
        av0 = *(const float4*)(ap_base);
        av1 = *(const float4*)(ap_base + 4);
    }
    float4 bv0 = *(const float4*)(bp_base);
    float4 bv1 = *(const float4*)(bp_base + 4);

    As[0][akc + 0][arow] = av0.x;  As[0][akc + 1][arow] = av0.y;
    As[0][akc + 2][arow] = av0.z;  As[0][akc + 3][arow] = av0.w;
    As[0][akc + 4][arow] = av1.x;  As[0][akc + 5][arow] = av1.y;
    As[0][akc + 6][arow] = av1.z;  As[0][akc + 7][arow] = av1.w;
    *(float4*)&Bs[0][bkr][bnc]     = bv0;
    *(float4*)&Bs[0][bkr][bnc + 4] = bv1;
    __syncthreads();

    constexpr int NC = Ddim / 16;
    for (int c = 0; c < NC; c++) {
        int cur = c & 1, nxt = cur ^ 1;
        if (c + 1 < NC) {
            int k0 = (c + 1) * 16;
            if (ap_base) {
                av0 = *(const float4*)(ap_base + k0);
                av1 = *(const float4*)(ap_base + k0 + 4);
            }
            const float* bp = bp_base + (size_t)k0 * Hdim;
            bv0 = *(const float4*)(bp);
            bv1 = *(const float4*)(bp + 4);
        }
#pragma unroll
        for (int kk = 0; kk < 16; kk++) {
            float4 aA = *(const float4*)&As[cur][kk][tm];
            float4 aB = *(const float4*)&As[cur][kk][tm + 4];
            ulonglong2 bA = *(const ulonglong2*)&Bs[cur][kk][tn];
            ulonglong2 bB = *(const ulonglong2*)&Bs[cur][kk][tn + 4];
            unsigned long long b2[4] = {bA.x, bA.y, bB.x, bB.y};
            float a[8] = {aA.x, aA.y, aA.z, aA.w, aB.x, aB.y, aB.z, aB.w};
#pragma unroll
            for (int i = 0; i < 8; i++) {
                unsigned long long ai = pack2(a[i]);
#pragma unroll
                for (int j = 0; j < 4; j++) fma2(acc[i][j], ai, b2[j]);
            }
        }
        if (c + 1 < NC) {
            As[nxt][akc + 0][arow] = av0.x;  As[nxt][akc + 1][arow] = av0.y;
            As[nxt][akc + 2][arow] = av0.z;  As[nxt][akc + 3][arow] = av0.w;
            As[nxt][akc + 4][arow] = av1.x;  As[nxt][akc + 5][arow] = av1.y;
            As[nxt][akc + 6][arow] = av1.z;  As[nxt][akc + 7][arow] = av1.w;
            *(float4*)&Bs[nxt][bkr][bnc]     = bv0;
            *(float4*)&Bs[nxt][bkr][bnc + 4] = bv1;
        }
        __syncthreads();
    }

    const float* b1p = b1 + (size_t)e * Hdim + n0 + tn;
#pragma unroll
    for (int i = 0; i < 8; i++) {
        int r = m0 + tm + i;
        if (r < cnt) {
            float* hp = g_h + (size_t)(base + r) * Hdim + n0 + tn;
#pragma unroll
            for (int j = 0; j < 4; j++) {
                float2 v = unpack2(acc[i][j]);
                float2 o;
                o.x = fmaxf(v.x + b1p[j * 2 + 0], 0.f);
                o.y = fmaxf(v.y + b1p[j * 2 + 1], 0.f);
                *(float2*)(hp + j * 2) = o;
            }
        }
    }
}

// ---------------- kernel 5: GEMM2 (K-split x5, atomic out) ----------------------
__global__ void __launch_bounds__(256, 2)
ffn2_kernel(const float* __restrict__ W2,
            const float* __restrict__ b2) {
    int ty = blockIdx.y;
    if (ty >= g_ntiles) return;
    int e = g_tile_e[ty];
    int cnt = g_cnt[e];
    int m0 = g_tile_m[ty] << 7;
    int base = g_off[e];
    int n0 = blockIdx.x * 128;
    int z = blockIdx.z;
    int cstart = (z < 2) ? z * 39 : 78 + (z - 2) * 38;
    int NC = (z < 2) ? 39 : 38;
    int kbase = cstart * 16;

    const float* Bp = W2 + (size_t)e * Hdim * Ddim;

    __shared__ float As[2][16][132];
    __shared__ float Bs[2][16][128];

    int tid = threadIdx.x;
    int arow = tid >> 1, akc = (tid & 1) * 8;
    int bkr = tid >> 4, bnc = (tid & 15) * 8;
    int tm = (tid >> 4) * 8, tn = (tid & 15) * 8;

    int r_a = m0 + arow;
    if (r_a >= cnt) r_a = cnt - 1;
    const float* ap_base = g_h + (size_t)(base + r_a) * Hdim + kbase + akc;
    const float* bp_base = Bp + (size_t)(kbase + bkr) * Ddim + n0 + bnc;

    unsigned long long acc[8][4];
#pragma unroll
    for (int i = 0; i < 8; i++)
#pragma unroll
        for (int j = 0; j < 4; j++) acc[i][j] = 0ull;

    float4 av0 = *(const float4*)(ap_base);
    float4 av1 = *(const float4*)(ap_base + 4);
    float4 bv0 = *(const float4*)(bp_base);
    float4 bv1 = *(const float4*)(bp_base + 4);

    As[0][akc + 0][arow] = av0.x;  As[0][akc + 1][arow] = av0.y;
    As[0][akc + 2][arow] = av0.z;  As[0][akc + 3][arow] = av0.w;
    As[0][akc + 4][arow] = av1.x;  As[0][akc + 5][arow] = av1.y;
    As[0][akc + 6][arow] = av1.z;  As[0][akc + 7][arow] = av1.w;
    *(float4*)&Bs[0][bkr][bnc]     = bv0;
    *(float4*)&Bs[0][bkr][bnc + 4] = bv1;
    __syncthreads();

    for (int c = 0; c < NC; c++) {
        int cur = c & 1, nxt = cur ^ 1;
        if (c + 1 < NC) {
            int k0 = (c + 1) * 16;
            av0 = *(const float4*)(ap_base + k0);
            av1 = *(const float4*)(ap_base + k0 + 4);
            const float* bp = bp_base + (size_t)k0 * Ddim;
            bv0 = *(const float4*)(bp);
            bv1 = *(const float4*)(bp + 4);
        }
#pragma unroll
        for (int kk = 0; kk < 16; kk++) {
            float4 aA = *(const float4*)&As[cur][kk][tm];
            float4 aB = *(const float4*)&As[cur][kk][tm + 4];
            ulonglong2 bA = *(const ulonglong2*)&Bs[cur][kk][tn];
            ulonglong2 bB = *(const ulonglong2*)&Bs[cur][kk][tn + 4];
            unsigned long long b2v[4] = {bA.x, bA.y, bB.x, bB.y};
            float a[8] = {aA.x, aA.y, aA.z, aA.w, aB.x, aB.y, aB.z, aB.w};
#pragma unroll
            for (int i = 0; i < 8; i++) {
                unsigned long long ai = pack2(a[i]);
#pragma unroll
                for (int j = 0; j < 4; j++) fma2(acc[i][j], ai, b2v[j]);
            }
        }
        if (c + 1 < NC) {
            As[nxt][akc + 0][arow] = av0.x;  As[nxt][akc + 1][arow] = av0.y;
            As[nxt][akc + 2][arow] = av0.z;  As[nxt][akc + 3][arow] = av0.w;
            As[nxt][akc + 4][arow] = av1.x;  As[nxt][akc + 5][arow] = av1.y;
            As[nxt][akc + 6][arow] = av1.z;  As[nxt][akc + 7][arow] = av1.w;
            *(float4*)&Bs[nxt][bkr][bnc]     = bv0;
            *(float4*)&Bs[nxt][bkr][bnc + 4] = bv1;
        }
        __syncthreads();
    }

    const float* b2p = b2 + (size_t)e * Ddim + n0 + tn;
#pragma unroll
    for (int i = 0; i < 8; i++) {
        int r = m0 + tm + i;
        if (r < cnt) {
            float g = g_gate[base + r];
            float* yp = g_yd + (size_t)(base + r) * Ddim + n0 + tn;
#pragma unroll
            for (int j = 0; j < 4; j++) {
                float2 v = unpack2(acc[i][j]);
                float p0 = g * v.x;
                float p1 = g * v.y;
                if (z == 0) {
                    p0 += g * b2p[j * 2 + 0];
                    p1 += g * b2p[j * 2 + 1];
                }
                atomicAdd(yp + j * 2 + 0, p0);
                atomicAdd(yp + j * 2 + 1, p1);
            }
        }
    }
}

// ---------------- kernel 6: combine ---------------------------------------------
__global__ void combine_kernel(float* __restrict__ out) {
    int idx = blockIdx.x * blockDim.x + threadIdx.x;
    int total = NTOK * Ddim / 4;
    if (idx >= total) return;
    int t = idx / (Ddim / 4);
    int d4 = idx % (Ddim / 4);
    int p0 = g_pos[t * 2 + 0];
    int p1 = g_pos[t * 2 + 1];
    float4 a = *(const float4*)(g_yd + (size_t)p0 * Ddim + d4 * 4);
    float4 b = *(const float4*)(g_yd + (size_t)p1 * Ddim + d4 * 4);
    float4 o;
    o.x = a.x + b.x; o.y = a.y + b.y; o.z = a.z + b.z; o.w = a.w + b.w;
    *(float4*)(out + (size_t)t * Ddim + d4 * 4) = o;
}

// ---------------- launch ---------------------------------------------------------
extern "C" void kernel_launch(void* const* d_in, const int* in_sizes, int n_in,
                              void* d_out, int out_size) {
    const float* x       = (const float*)d_in[0];
    const float* noise   = (const float*)d_in[1];
    const float* w_route = (const float*)d_in[2];
    const float* b_route = (const float*)d_in[3];
    const float* w_noise = (const float*)d_in[4];
    const float* b_noise = (const float*)d_in[5];
    const float* W1      = (const float*)d_in[6];
    const float* b1      = (const float*)d_in[7];
    const float* W2      = (const float*)d_in[8];
    const float* b2      = (const float*)d_in[9];
    float* out = (float*)d_out;

    zero_kernel<<<1, 32>>>();
    router_kernel<<<NTOK / 8, 256>>>(x, noise, w_route, b_route, w_noise, b_noise);
    scan_kernel<<<1, 1>>>();
    fill_kernel<<<(NDISP + 255) / 256, 256>>>();
    yzero_kernel<<<(NDISP * (Ddim / 4) + 255) / 256, 256>>>();
    ffn1_kernel<<<dim3(Hdim / 128, MAXTILES), 256>>>(x, W1, b1);
    ffn2_kernel<<<dim3(Ddim / 128, MAXTILES, KSPLIT), 256>>>(W2, b2);
    combine_kernel<<<(NTOK * Ddim / 4 + 255) / 256, 256>>>(out);
}